// round 7
// baseline (speedup 1.0000x reference)
#include <cuda_runtime.h>
#include <cuda_fp16.h>
#include <cuda_fp8.h>
#include <cstdint>

// ---------------------------------------------------------------------------
// LinearAttention on GB300 (sm_103a via compute_103 PTX)
// Round 7: fp16-main + e4m3-correction GEMMs. Fixes R6's misaligned cp.async
// (fp8 pitch 72 -> 80, lo-half offset 36 -> 48; all 16B-aligned).
// x*y = xh*yh (fp16 mma) + [xl*yh + xh*yl] (e4m3 mma, lo pre-scaled 2^12)
// B=4, S=4096, D=1024, H=16, hd=64
// ---------------------------------------------------------------------------

#define BATCH 4
#define SEQ   4096
#define EMB   1024
#define HEADS 16
#define HDIM  64
#define ROWS  (BATCH * SEQ)     // 16384
#define BH    (BATCH * HEADS)   // 64
#define SPLITS 16
#define SROWS (SEQ / SPLITS)    // 256

#define CSCALE 4096.0f
#define CINV   (1.0f / 4096.0f)

// GEMM tiling
#define MT 128
#define NTT 128
#define KC 32
#define KCH (EMB / KC)          // 32
#define STAGES 3
#define G_THREADS 256
// fp16 rows: 32 halfs + 16B pad = 80B pitch
// fp8 rows:  [h8 32B | pad 16B | l8 32B] = 80B pitch (all cp.async dsts 16B-aligned)
#define PITCH16B 80
#define PITCH8B  80
#define L8OFF    48
#define SZ_H16  (MT * PITCH16B)          // 10240
#define SZ_F8   (MT * PITCH8B)           // 10240
#define OFF_AH  0
#define OFF_BH  (SZ_H16)
#define OFF_A8  (2 * SZ_H16)
#define OFF_B8  (2 * SZ_H16 + SZ_F8)
#define STAGE_BYTES (2 * SZ_H16 + 2 * SZ_F8)   // 40960
#define SMEM_DYN (STAGES * STAGE_BYTES)        // 122880

// ---------------------------------------------------------------------------
// Scratch (__device__ globals; allocation-free per harness rules)
// ---------------------------------------------------------------------------
__device__ __align__(256) float g_Q[(size_t)ROWS * EMB];
__device__ __align__(256) float g_K[(size_t)ROWS * EMB];
__device__ __align__(256) float g_V[(size_t)ROWS * EMB];
// activation operand (hi fp16, hi/lo e4m3)
__device__ __align__(256) __half  g_Xh[(size_t)ROWS * EMB];
__device__ __align__(256) uint8_t g_X8h[(size_t)ROWS * EMB];
__device__ __align__(256) uint8_t g_X8l[(size_t)ROWS * EMB];
// weights (transposed [n][k]), 4 sets
__device__ __align__(256) __half  g_Wh[4][(size_t)EMB * EMB];
__device__ __align__(256) uint8_t g_W8h[4][(size_t)EMB * EMB];
__device__ __align__(256) uint8_t g_W8l[4][(size_t)EMB * EMB];
// attention core
__device__ float g_KVp[(size_t)SPLITS * BH * HDIM * HDIM];
__device__ float g_Ksump[(size_t)SPLITS * BH * HDIM];
__device__ float g_KV[(size_t)BH * HDIM * HDIM];
__device__ float g_Ksum[(size_t)BH * HDIM];

// ---------------------------------------------------------------------------
// helpers
// ---------------------------------------------------------------------------
__device__ __forceinline__ uint32_t smem_u32(const void* p) {
    uint32_t a;
    asm("{ .reg .u64 t; cvta.to.shared.u64 t, %1; cvt.u32.u64 %0, t; }" : "=r"(a) : "l"(p));
    return a;
}
__device__ __forceinline__ void cp16(uint32_t saddr, const void* gaddr) {
    asm volatile("cp.async.cg.shared.global [%0], [%1], 16;" :: "r"(saddr), "l"(gaddr) : "memory");
}
__device__ __forceinline__ void ldsm4(uint32_t& r0, uint32_t& r1, uint32_t& r2,
                                      uint32_t& r3, uint32_t addr) {
    asm volatile("ldmatrix.sync.aligned.m8n8.x4.shared.b16 {%0,%1,%2,%3}, [%4];"
                 : "=r"(r0), "=r"(r1), "=r"(r2), "=r"(r3) : "r"(addr));
}
__device__ __forceinline__ void mma_f16(float* c, const uint32_t* a, const uint32_t* b) {
    asm volatile(
        "mma.sync.aligned.m16n8k16.row.col.f32.f16.f16.f32 "
        "{%0,%1,%2,%3}, {%4,%5,%6,%7}, {%8,%9}, {%0,%1,%2,%3};"
        : "+f"(c[0]), "+f"(c[1]), "+f"(c[2]), "+f"(c[3])
        : "r"(a[0]), "r"(a[1]), "r"(a[2]), "r"(a[3]), "r"(b[0]), "r"(b[1]));
}
__device__ __forceinline__ void mma_e4m3(float* c, const uint32_t* a, const uint32_t* b) {
    asm volatile(
        "mma.sync.aligned.m16n8k32.row.col.f32.e4m3.e4m3.f32 "
        "{%0,%1,%2,%3}, {%4,%5,%6,%7}, {%8,%9}, {%0,%1,%2,%3};"
        : "+f"(c[0]), "+f"(c[1]), "+f"(c[2]), "+f"(c[3])
        : "r"(a[0]), "r"(a[1]), "r"(a[2]), "r"(a[3]), "r"(b[0]), "r"(b[1]));
}
__device__ __forceinline__ uint8_t to_e4m3(float x) {
    return (uint8_t)__nv_cvt_float_to_fp8(x, __NV_SATFINITE, __NV_E4M3);
}

// ---------------------------------------------------------------------------
// GEMM: C[M,N] = A @ Bt^T + bias (+elu+1)
// A rows: Ah(fp16), A8h/A8l(e4m3); Bt rows [n][k]: same triplet.
// Grid (8, 128), 256 threads, warp tile 64x32, 3-stage cp.async.
// ---------------------------------------------------------------------------
__global__ __launch_bounds__(G_THREADS) void gemm_mp(
    const __half* __restrict__ Ah, const uint8_t* __restrict__ A8h,
    const uint8_t* __restrict__ A8l,
    const __half* __restrict__ Bh, const uint8_t* __restrict__ B8h,
    const uint8_t* __restrict__ B8l,
    const float* __restrict__ bias, float* __restrict__ C, int elu_mode)
{
    extern __shared__ char dsm[];
    const uint32_t dyn = smem_u32(dsm);

    const int tid  = threadIdx.x;
    const int wid  = tid >> 5;
    const int lane = tid & 31;
    const int m0 = blockIdx.y * MT;
    const int n0 = blockIdx.x * NTT;
    const int wm = (wid >> 2) * 64;     // warp row offset (0 / 64)
    const int wn = (wid & 3) * 32;      // warp col offset (0/32/64/96)

    // ---- stage loader: 2048 x 16B granules ----
    auto load_stage = [&](int ch) {
        const int st = ch % STAGES;
        const uint32_t sb = dyn + (uint32_t)st * STAGE_BYTES;
        const int k0 = ch * KC;
        #pragma unroll
        for (int i = tid; i < 2048; i += G_THREADS) {
            const int sec = i >> 9;          // 0 Ah, 1 Bh, 2 A8, 3 B8
            const int rem = i & 511;
            const int rr  = rem >> 2;
            const int g   = rem & 3;
            if (sec == 0) {
                cp16(sb + OFF_AH + (uint32_t)rr * PITCH16B + g * 16u,
                     Ah + (size_t)(m0 + rr) * EMB + k0 + g * 8);
            } else if (sec == 1) {
                cp16(sb + OFF_BH + (uint32_t)rr * PITCH16B + g * 16u,
                     Bh + (size_t)(n0 + rr) * EMB + k0 + g * 8);
            } else if (sec == 2) {
                if (g < 2)
                    cp16(sb + OFF_A8 + (uint32_t)rr * PITCH8B + g * 16u,
                         A8h + (size_t)(m0 + rr) * EMB + k0 + g * 16);
                else
                    cp16(sb + OFF_A8 + (uint32_t)rr * PITCH8B + L8OFF + (g - 2) * 16u,
                         A8l + (size_t)(m0 + rr) * EMB + k0 + (g - 2) * 16);
            } else {
                if (g < 2)
                    cp16(sb + OFF_B8 + (uint32_t)rr * PITCH8B + g * 16u,
                         B8h + (size_t)(n0 + rr) * EMB + k0 + g * 16);
                else
                    cp16(sb + OFF_B8 + (uint32_t)rr * PITCH8B + L8OFF + (g - 2) * 16u,
                         B8l + (size_t)(n0 + rr) * EMB + k0 + (g - 2) * 16);
            }
        }
        asm volatile("cp.async.commit_group;" ::: "memory");
    };

    float accm[4][4][4];
    float accc[4][4][4];
    #pragma unroll
    for (int i = 0; i < 4; i++)
        #pragma unroll
        for (int j = 0; j < 4; j++)
            #pragma unroll
            for (int q = 0; q < 4; q++) { accm[i][j][q] = 0.f; accc[i][j][q] = 0.f; }

    #pragma unroll
    for (int s = 0; s < STAGES - 1; s++) load_stage(s);

    for (int ch = 0; ch < KCH; ch++) {
        if (ch + STAGES - 1 < KCH) load_stage(ch + STAGES - 1);
        else asm volatile("cp.async.commit_group;" ::: "memory");
        asm volatile("cp.async.wait_group %0;" :: "n"(STAGES - 1) : "memory");
        __syncthreads();

        const uint32_t soff = (uint32_t)(ch % STAGES) * STAGE_BYTES;
        const uint32_t sb = dyn + soff;
        const char* sm = dsm + soff;

        // ---- main term: fp16 m16n8k16, two k-halves ----
        #pragma unroll
        for (int ks = 0; ks < 2; ks++) {
            const int kl = ks * 16;
            const int a_row = wm + (lane & 15);
            const int a_col = kl + (lane >> 4) * 8;
            const int b_row = wn + (lane & 7) + ((lane >> 4) & 1) * 8;
            const int b_col = kl + ((lane >> 3) & 1) * 8;

            uint32_t ah[4][4];
            #pragma unroll
            for (int fm = 0; fm < 4; fm++) {
                uint32_t off = (uint32_t)(a_row + fm * 16) * PITCH16B + (uint32_t)a_col * 2u;
                ldsm4(ah[fm][0], ah[fm][1], ah[fm][2], ah[fm][3], sb + OFF_AH + off);
            }
            uint32_t bh[2][4];
            #pragma unroll
            for (int fp = 0; fp < 2; fp++) {
                uint32_t off = (uint32_t)(b_row + fp * 16) * PITCH16B + (uint32_t)b_col * 2u;
                ldsm4(bh[fp][0], bh[fp][1], bh[fp][2], bh[fp][3], sb + OFF_BH + off);
            }
            #pragma unroll
            for (int fm = 0; fm < 4; fm++)
                #pragma unroll
                for (int fn = 0; fn < 4; fn++)
                    mma_f16(accm[fm][fn], ah[fm], &bh[fn >> 1][(fn & 1) * 2]);
        }

        // ---- correction terms: e4m3 m16n8k32 ----
        {
            const int tig = lane & 3, grp = lane >> 2;
            // B fragments (hoisted: 4 n8-blocks x {h,l})
            uint32_t b8h[4][2], b8l[4][2];
            #pragma unroll
            for (int fn = 0; fn < 4; fn++) {
                const char* bp = sm + OFF_B8 + (size_t)(wn + fn * 8 + grp) * PITCH8B + tig * 4;
                b8h[fn][0] = *(const uint32_t*)(bp);
                b8h[fn][1] = *(const uint32_t*)(bp + 16);
                b8l[fn][0] = *(const uint32_t*)(bp + L8OFF);
                b8l[fn][1] = *(const uint32_t*)(bp + L8OFF + 16);
            }
            #pragma unroll
            for (int fm = 0; fm < 4; fm++) {
                const char* a0 = sm + OFF_A8 + (size_t)(wm + fm * 16 + grp) * PITCH8B + tig * 4;
                const char* a1 = a0 + 8 * PITCH8B;
                uint32_t a8h[4], a8l[4];
                a8h[0] = *(const uint32_t*)(a0);          a8h[1] = *(const uint32_t*)(a1);
                a8h[2] = *(const uint32_t*)(a0 + 16);     a8h[3] = *(const uint32_t*)(a1 + 16);
                a8l[0] = *(const uint32_t*)(a0 + L8OFF);  a8l[1] = *(const uint32_t*)(a1 + L8OFF);
                a8l[2] = *(const uint32_t*)(a0 + L8OFF + 16);
                a8l[3] = *(const uint32_t*)(a1 + L8OFF + 16);
                #pragma unroll
                for (int fn = 0; fn < 4; fn++) {
                    mma_e4m3(accc[fm][fn], a8l, b8h[fn]);   // Al*Bh (x4096)
                    mma_e4m3(accc[fm][fn], a8h, b8l[fn]);   // Ah*Bl (x4096)
                }
            }
        }
        __syncthreads();
    }

    // ---- epilogue: merge, bias (+elu+1) ----
    const int er = lane >> 2;           // 0..7
    const int ec = (lane & 3) * 2;      // 0,2,4,6
    #pragma unroll
    for (int fn = 0; fn < 4; fn++) {
        const int col = n0 + wn + fn * 8 + ec;
        const float b0 = bias[col], b1 = bias[col + 1];
        #pragma unroll
        for (int fm = 0; fm < 4; fm++) {
            const int row = m0 + wm + fm * 16 + er;
            #pragma unroll
            for (int h = 0; h < 2; h++) {
                float v0 = accm[fm][fn][2 * h + 0] + accc[fm][fn][2 * h + 0] * CINV + b0;
                float v1 = accm[fm][fn][2 * h + 1] + accc[fm][fn][2 * h + 1] * CINV + b1;
                if (elu_mode) {
                    v0 = (v0 > 0.f) ? (v0 + 1.f) : __expf(v0);
                    v1 = (v1 > 0.f) ? (v1 + 1.f) : __expf(v1);
                }
                *(float2*)(C + (size_t)(row + 8 * h) * EMB + col) = make_float2(v0, v1);
            }
        }
    }
}

// ---------------------------------------------------------------------------
// fp32 -> (fp16 hi, e4m3 hi, e4m3 lo*4096) split
// ---------------------------------------------------------------------------
__global__ __launch_bounds__(256) void conv_split(
    const float* __restrict__ X, __half* __restrict__ H,
    uint8_t* __restrict__ H8, uint8_t* __restrict__ L8)
{
    size_t i = ((size_t)blockIdx.x * 256 + threadIdx.x) * 4;
    float4 v = *(const float4*)(X + i);
    const float* vp = (const float*)&v;
    ushort4 hv; uchar4 h8v, l8v;
    unsigned short* hp = (unsigned short*)&hv;
    unsigned char* h8p = (unsigned char*)&h8v;
    unsigned char* l8p = (unsigned char*)&l8v;
    #pragma unroll
    for (int j = 0; j < 4; j++) {
        float x = vp[j];
        __half h = __float2half_rn(x);
        float l = x - __half2float(h);
        hp[j]  = __half_as_ushort(h);
        h8p[j] = to_e4m3(x);
        l8p[j] = to_e4m3(l * CSCALE);
    }
    *(ushort4*)(H + i) = hv;
    *(uchar4*)(H8 + i) = h8v;
    *(uchar4*)(L8 + i) = l8v;
}

// ---------------------------------------------------------------------------
// Weight transpose + split: Wt[n][k] = W[k][n]
// ---------------------------------------------------------------------------
__global__ __launch_bounds__(256) void conv_w_t(
    const float* __restrict__ W, __half* __restrict__ H,
    uint8_t* __restrict__ H8, uint8_t* __restrict__ L8)
{
    __shared__ float tile[32][33];
    const int n0 = blockIdx.x * 32, k0 = blockIdx.y * 32;
    const int tx = threadIdx.x & 31, ty = threadIdx.x >> 5;  // 32x8
    #pragma unroll
    for (int j = 0; j < 32; j += 8)
        tile[ty + j][tx] = W[(size_t)(k0 + ty + j) * EMB + n0 + tx];
    __syncthreads();
    #pragma unroll
    for (int j = 0; j < 32; j += 8) {
        float x = tile[tx][ty + j];
        __half h = __float2half_rn(x);
        float l = x - __half2float(h);
        size_t o = (size_t)(n0 + ty + j) * EMB + k0 + tx;
        H[o]  = h;
        H8[o] = to_e4m3(x);
        L8[o] = to_e4m3(l * CSCALE);
    }
}

// ---------------------------------------------------------------------------
// KV summarization: KV[b,h,d,e] = sum_s K[:,d]*V[:,e]; Ksum[b,h,d]
// Register-tiled 4x4 per thread, float4 LDS.
// ---------------------------------------------------------------------------
#define KVCH 16

__global__ __launch_bounds__(256) void kv_partial()
{
    const int bh = blockIdx.x, sp = blockIdx.y;
    const int b = bh / HEADS, h = bh % HEADS;
    const int t = threadIdx.x;
    const int d0 = (t & 15) * 4;
    const int e0 = (t >> 4) * 4;

    __shared__ float Ks[KVCH][HDIM];
    __shared__ float Vs[KVCH][HDIM];

    float acc[4][4];
    #pragma unroll
    for (int i = 0; i < 4; i++)
        #pragma unroll
        for (int j = 0; j < 4; j++) acc[i][j] = 0.f;
    float ksum[4] = {0.f, 0.f, 0.f, 0.f};

    const float* Kbase = g_K + (size_t)b * SEQ * EMB + h * HDIM;
    const float* Vbase = g_V + (size_t)b * SEQ * EMB + h * HDIM;

    const int lr = t >> 4, lc = (t & 15) * 4;   // load mapping: 16 rows x 16 float4
    const int s_begin = sp * SROWS;
    for (int s0 = s_begin; s0 < s_begin + SROWS; s0 += KVCH) {
        *(float4*)&Ks[lr][lc] = *(const float4*)(Kbase + (size_t)(s0 + lr) * EMB + lc);
        *(float4*)&Vs[lr][lc] = *(const float4*)(Vbase + (size_t)(s0 + lr) * EMB + lc);
        __syncthreads();
        #pragma unroll
        for (int ss = 0; ss < KVCH; ss++) {
            float4 kk = *(const float4*)&Ks[ss][d0];
            float4 vv = *(const float4*)&Vs[ss][e0];
            const float* kp = (const float*)&kk;
            const float* vp = (const float*)&vv;
            #pragma unroll
            for (int i = 0; i < 4; i++) {
                ksum[i] += kp[i];
                #pragma unroll
                for (int j = 0; j < 4; j++)
                    acc[i][j] += kp[i] * vp[j];
            }
        }
        __syncthreads();
    }

    float* KVp = g_KVp + ((size_t)sp * BH + bh) * HDIM * HDIM;
    #pragma unroll
    for (int i = 0; i < 4; i++)
        *(float4*)(KVp + (size_t)(d0 + i) * HDIM + e0) = *(float4*)acc[i];
    if (t < 16) {
        #pragma unroll
        for (int i = 0; i < 4; i++)
            g_Ksump[((size_t)sp * BH + bh) * HDIM + d0 + i] = ksum[i];
    }
}

__global__ __launch_bounds__(256) void kv_reduce()
{
    const int bh = blockIdx.x;
    const int t = threadIdx.x;
    for (int i = t; i < HDIM * HDIM; i += 256) {
        float s = 0.f;
        #pragma unroll
        for (int sp = 0; sp < SPLITS; sp++)
            s += g_KVp[((size_t)sp * BH + bh) * HDIM * HDIM + i];
        g_KV[(size_t)bh * HDIM * HDIM + i] = s;
    }
    if (t < HDIM) {
        float s = 0.f;
        #pragma unroll
        for (int sp = 0; sp < SPLITS; sp++)
            s += g_Ksump[((size_t)sp * BH + bh) * HDIM + t];
        g_Ksum[(size_t)bh * HDIM + t] = s;
    }
}

// ---------------------------------------------------------------------------
// Apply: attn = (Q·KV)/(Q·Ksum+1e-6); writes fp16 + e4m3 hi/lo directly.
// Q staged transposed for float4 row reads. 4x4 register tile.
// ---------------------------------------------------------------------------
__global__ __launch_bounds__(256) void apply_attn()
{
    const int stile = blockIdx.x;
    const int bh = blockIdx.y;
    const int b = bh / HEADS, h = bh % HEADS;
    const int t = threadIdx.x;

    __shared__ float Qt[HDIM][64];      // Qt[d][row]
    __shared__ float KVs[HDIM][HDIM];
    __shared__ float Ksums[HDIM];

    const int s0 = stile * 64;
    const float* Qbase = g_Q + (size_t)(b * SEQ + s0) * EMB + h * HDIM;

    #pragma unroll
    for (int k = 0; k < 16; k++) {
        int idx = t + 256 * k;
        int rr = idx >> 6, cc = idx & 63;
        Qt[cc][rr] = Qbase[(size_t)rr * EMB + cc];
        KVs[rr][cc] = g_KV[(size_t)bh * HDIM * HDIM + idx];
    }
    if (t < HDIM) Ksums[t] = g_Ksum[(size_t)bh * HDIM + t];
    __syncthreads();

    const int r0 = (t & 15) * 4;
    const int e0 = (t >> 4) * 4;

    float acc[4][4];
    #pragma unroll
    for (int i = 0; i < 4; i++)
        #pragma unroll
        for (int j = 0; j < 4; j++) acc[i][j] = 0.f;
    float nrm[4] = {0.f, 0.f, 0.f, 0.f};

    #pragma unroll
    for (int dd = 0; dd < HDIM; dd++) {
        float4 qq = *(const float4*)&Qt[dd][r0];
        float4 vv = *(const float4*)&KVs[dd][e0];
        const float* qp = (const float*)&qq;
        const float* vp = (const float*)&vv;
        float ks = Ksums[dd];
        #pragma unroll
        for (int i = 0; i < 4; i++) {
            nrm[i] += qp[i] * ks;
            #pragma unroll
            for (int j = 0; j < 4; j++)
                acc[i][j] += qp[i] * vp[j];
        }
    }

    #pragma unroll
    for (int i = 0; i < 4; i++) {
        float inv = 1.f / (nrm[i] + 1e-6f);
        size_t obase = (size_t)(b * SEQ + s0 + r0 + i) * EMB + h * HDIM + e0;
        ushort4 hv; uchar4 h8v, l8v;
        unsigned short* hp = (unsigned short*)&hv;
        unsigned char* h8p = (unsigned char*)&h8v;
        unsigned char* l8p = (unsigned char*)&l8v;
        #pragma unroll
        for (int j = 0; j < 4; j++) {
            float x = acc[i][j] * inv;
            __half hh = __float2half_rn(x);
            float l = x - __half2float(hh);
            hp[j]  = __half_as_ushort(hh);
            h8p[j] = to_e4m3(x);
            l8p[j] = to_e4m3(l * CSCALE);
        }
        *(ushort4*)(g_Xh + obase) = hv;
        *(uchar4*)(g_X8h + obase) = h8v;
        *(uchar4*)(g_X8l + obase) = l8v;
    }
}

// ---------------------------------------------------------------------------
// Launch
// ---------------------------------------------------------------------------
extern "C" void kernel_launch(void* const* d_in, const int* in_sizes, int n_in,
                              void* d_out, int out_size)
{
    const float* query = (const float*)d_in[0];
    const float* keyv  = (const float*)d_in[1];
    const float* W[4] = { (const float*)d_in[2], (const float*)d_in[4],
                          (const float*)d_in[6], (const float*)d_in[8] };
    const float* bq = (const float*)d_in[3];
    const float* bk = (const float*)d_in[5];
    const float* bv = (const float*)d_in[7];
    const float* bo = (const float*)d_in[9];
    float* out = (float*)d_out;

    float *pQ, *pK, *pV;
    __half *pXh; uint8_t *pX8h, *pX8l;
    __half (*pWh)[(size_t)EMB * EMB];
    uint8_t (*pW8h)[(size_t)EMB * EMB], (*pW8l)[(size_t)EMB * EMB];
    cudaGetSymbolAddress((void**)&pQ, g_Q);
    cudaGetSymbolAddress((void**)&pK, g_K);
    cudaGetSymbolAddress((void**)&pV, g_V);
    cudaGetSymbolAddress((void**)&pXh, g_Xh);
    cudaGetSymbolAddress((void**)&pX8h, g_X8h);
    cudaGetSymbolAddress((void**)&pX8l, g_X8l);
    cudaGetSymbolAddress((void**)&pWh, g_Wh);
    cudaGetSymbolAddress((void**)&pW8h, g_W8h);
    cudaGetSymbolAddress((void**)&pW8l, g_W8l);

    static bool attr_set = false;
    if (!attr_set) {
        cudaFuncSetAttribute(gemm_mp, cudaFuncAttributeMaxDynamicSharedMemorySize, SMEM_DYN);
        attr_set = true;
    }

    const dim3 wgrid(EMB / 32, EMB / 32);              // (32, 32)
    const dim3 ggrid(EMB / NTT, ROWS / MT);            // (8, 128)
    const int conv_blocks = (int)(((size_t)ROWS * EMB / 4) / 256);  // 16384

    // Weight transpose + split
    for (int w = 0; w < 4; w++)
        conv_w_t<<<wgrid, 256>>>(W[w], pWh[w], pW8h[w], pW8l[w]);

    // Q projection (elu+1 fused)
    conv_split<<<conv_blocks, 256>>>(query, pXh, pX8h, pX8l);
    gemm_mp<<<ggrid, G_THREADS, SMEM_DYN>>>(pXh, pX8h, pX8l,
                                            pWh[0], pW8h[0], pW8l[0], bq, pQ, 1);

    // K/V projections (share key_value conversion)
    conv_split<<<conv_blocks, 256>>>(keyv, pXh, pX8h, pX8l);
    gemm_mp<<<ggrid, G_THREADS, SMEM_DYN>>>(pXh, pX8h, pX8l,
                                            pWh[1], pW8h[1], pW8l[1], bk, pK, 1);
    gemm_mp<<<ggrid, G_THREADS, SMEM_DYN>>>(pXh, pX8h, pX8l,
                                            pWh[2], pW8h[2], pW8l[2], bv, pV, 0);

    // Linear-attention core (fp32)
    kv_partial<<<dim3(BH, SPLITS), 256>>>();
    kv_reduce<<<BH, 256>>>();
    apply_attn<<<dim3(SEQ / 64, BH), 256>>>();   // emits fp16+e4m3 operand

    // Output projection
    gemm_mp<<<ggrid, G_THREADS, SMEM_DYN>>>(pXh, pX8h, pX8l,
                                            pWh[3], pW8h[3], pW8l[3], bo, out, 0);
}

// round 8
// speedup vs baseline: 2.6695x; 2.6695x over previous
#include <cuda_runtime.h>
#include <cuda_fp16.h>
#include <cstdint>

// ---------------------------------------------------------------------------
// LinearAttention on GB300 (sm_103a via compute_103 PTX)
// Round 8: single-term fp16 mma.sync GEMMs (3x less tensor work than R4's
// bf16 hi/lo; legacy HMMA pipe is the binding resource). fp32 attention core.
// B=4, S=4096, D=1024, H=16, hd=64
// ---------------------------------------------------------------------------

#define BATCH 4
#define SEQ   4096
#define EMB   1024
#define HEADS 16
#define HDIM  64
#define ROWS  (BATCH * SEQ)     // 16384
#define BH    (BATCH * HEADS)   // 64
#define SPLITS 16
#define SROWS (SEQ / SPLITS)    // 256

// GEMM tiling
#define MT 128
#define NTT 128
#define KC 32
#define KCH (EMB / KC)          // 32
#define STAGES 3
#define G_THREADS 256
// fp16 rows: 32 halfs (64B) + 16B pad = 80B pitch (ldmatrix conflict-free)
#define PITCH16B 80
#define SZ_H16  (MT * PITCH16B)          // 10240
#define OFF_AH  0
#define OFF_BH  (SZ_H16)
#define STAGE_BYTES (2 * SZ_H16)         // 20480
#define SMEM_DYN (STAGES * STAGE_BYTES)  // 61440  -> 2 CTAs/SM

// ---------------------------------------------------------------------------
// Scratch (__device__ globals; allocation-free per harness rules)
// ---------------------------------------------------------------------------
__device__ __align__(256) float g_Q[(size_t)ROWS * EMB];
__device__ __align__(256) float g_K[(size_t)ROWS * EMB];
__device__ __align__(256) float g_V[(size_t)ROWS * EMB];
__device__ __align__(256) __half g_Xh[(size_t)ROWS * EMB];      // GEMM A operand
__device__ __align__(256) __half g_Wh[4][(size_t)EMB * EMB];    // weights [n][k]
__device__ float g_KVp[(size_t)SPLITS * BH * HDIM * HDIM];
__device__ float g_Ksump[(size_t)SPLITS * BH * HDIM];
__device__ float g_KV[(size_t)BH * HDIM * HDIM];
__device__ float g_Ksum[(size_t)BH * HDIM];

// ---------------------------------------------------------------------------
// helpers
// ---------------------------------------------------------------------------
__device__ __forceinline__ uint32_t smem_u32(const void* p) {
    uint32_t a;
    asm("{ .reg .u64 t; cvta.to.shared.u64 t, %1; cvt.u32.u64 %0, t; }" : "=r"(a) : "l"(p));
    return a;
}
__device__ __forceinline__ void cp16(uint32_t saddr, const void* gaddr) {
    asm volatile("cp.async.cg.shared.global [%0], [%1], 16;" :: "r"(saddr), "l"(gaddr) : "memory");
}
__device__ __forceinline__ void ldsm4(uint32_t& r0, uint32_t& r1, uint32_t& r2,
                                      uint32_t& r3, uint32_t addr) {
    asm volatile("ldmatrix.sync.aligned.m8n8.x4.shared.b16 {%0,%1,%2,%3}, [%4];"
                 : "=r"(r0), "=r"(r1), "=r"(r2), "=r"(r3) : "r"(addr));
}
__device__ __forceinline__ void mma_f16(float* c, const uint32_t* a, const uint32_t* b) {
    asm volatile(
        "mma.sync.aligned.m16n8k16.row.col.f32.f16.f16.f32 "
        "{%0,%1,%2,%3}, {%4,%5,%6,%7}, {%8,%9}, {%0,%1,%2,%3};"
        : "+f"(c[0]), "+f"(c[1]), "+f"(c[2]), "+f"(c[3])
        : "r"(a[0]), "r"(a[1]), "r"(a[2]), "r"(a[3]), "r"(b[0]), "r"(b[1]));
}

// ---------------------------------------------------------------------------
// GEMM: C[M,N] = A @ Bt^T + bias (+elu+1); A,Bt fp16; C fp32.
// Grid (8, 128), 256 threads, warp tile 64x32, 3-stage cp.async, 2 CTAs/SM.
// ---------------------------------------------------------------------------
__global__ __launch_bounds__(G_THREADS, 2) void gemm_f16(
    const __half* __restrict__ A, const __half* __restrict__ B,
    const float* __restrict__ bias, float* __restrict__ C, int elu_mode)
{
    extern __shared__ char dsm[];
    const uint32_t dyn = smem_u32(dsm);

    const int tid  = threadIdx.x;
    const int wid  = tid >> 5;
    const int lane = tid & 31;
    const int m0 = blockIdx.y * MT;
    const int n0 = blockIdx.x * NTT;
    const int wm = (wid >> 2) * 64;     // warp row offset (0 / 64)
    const int wn = (wid & 3) * 32;      // warp col offset (0/32/64/96)

    // stage loader: A 128x4 + B 128x4 granules (16B) = 1024, 4 per thread
    auto load_stage = [&](int ch) {
        const int st = ch % STAGES;
        const uint32_t sb = dyn + (uint32_t)st * STAGE_BYTES;
        const int k0 = ch * KC;
        #pragma unroll
        for (int i = tid; i < 1024; i += G_THREADS) {
            const int half = i >> 9;         // 0=A 1=B
            const int rem  = i & 511;
            const int rr   = rem >> 2;
            const int g    = rem & 3;
            const __half* gp = half ? B : A;
            const int row = (half ? n0 : m0) + rr;
            cp16(sb + (uint32_t)half * SZ_H16 + (uint32_t)rr * PITCH16B + g * 16u,
                 gp + (size_t)row * EMB + k0 + g * 8);
        }
        asm volatile("cp.async.commit_group;" ::: "memory");
    };

    float acc[4][4][4];
    #pragma unroll
    for (int i = 0; i < 4; i++)
        #pragma unroll
        for (int j = 0; j < 4; j++)
            #pragma unroll
            for (int q = 0; q < 4; q++) acc[i][j][q] = 0.f;

    #pragma unroll
    for (int s = 0; s < STAGES - 1; s++) load_stage(s);

    for (int ch = 0; ch < KCH; ch++) {
        if (ch + STAGES - 1 < KCH) load_stage(ch + STAGES - 1);
        else asm volatile("cp.async.commit_group;" ::: "memory");
        asm volatile("cp.async.wait_group %0;" :: "n"(STAGES - 1) : "memory");
        __syncthreads();

        const uint32_t sb = dyn + (uint32_t)(ch % STAGES) * STAGE_BYTES;

        #pragma unroll
        for (int ks = 0; ks < 2; ks++) {
            const int kl = ks * 16;
            const int a_row = wm + (lane & 15);
            const int a_col = kl + (lane >> 4) * 8;
            const int b_row = wn + (lane & 7) + ((lane >> 4) & 1) * 8;
            const int b_col = kl + ((lane >> 3) & 1) * 8;

            uint32_t af[4][4];
            #pragma unroll
            for (int fm = 0; fm < 4; fm++) {
                uint32_t off = (uint32_t)(a_row + fm * 16) * PITCH16B + (uint32_t)a_col * 2u;
                ldsm4(af[fm][0], af[fm][1], af[fm][2], af[fm][3], sb + OFF_AH + off);
            }
            uint32_t bf[2][4];
            #pragma unroll
            for (int fp = 0; fp < 2; fp++) {
                uint32_t off = (uint32_t)(b_row + fp * 16) * PITCH16B + (uint32_t)b_col * 2u;
                ldsm4(bf[fp][0], bf[fp][1], bf[fp][2], bf[fp][3], sb + OFF_BH + off);
            }
            #pragma unroll
            for (int fm = 0; fm < 4; fm++)
                #pragma unroll
                for (int fn = 0; fn < 4; fn++)
                    mma_f16(acc[fm][fn], af[fm], &bf[fn >> 1][(fn & 1) * 2]);
        }
        __syncthreads();
    }

    // ---- epilogue: bias (+elu+1), fp32 stores ----
    const int er = lane >> 2;           // 0..7
    const int ec = (lane & 3) * 2;      // 0,2,4,6
    #pragma unroll
    for (int fn = 0; fn < 4; fn++) {
        const int col = n0 + wn + fn * 8 + ec;
        const float b0 = bias[col], b1 = bias[col + 1];
        #pragma unroll
        for (int fm = 0; fm < 4; fm++) {
            const int row = m0 + wm + fm * 16 + er;
            #pragma unroll
            for (int h = 0; h < 2; h++) {
                float v0 = acc[fm][fn][2 * h + 0] + b0;
                float v1 = acc[fm][fn][2 * h + 1] + b1;
                if (elu_mode) {
                    v0 = (v0 > 0.f) ? (v0 + 1.f) : __expf(v0);
                    v1 = (v1 > 0.f) ? (v1 + 1.f) : __expf(v1);
                }
                *(float2*)(C + (size_t)(row + 8 * h) * EMB + col) = make_float2(v0, v1);
            }
        }
    }
}

// ---------------------------------------------------------------------------
// fp32 -> fp16 (elementwise, float4-vectorized)
// ---------------------------------------------------------------------------
__global__ __launch_bounds__(256) void conv_f16(
    const float* __restrict__ X, __half* __restrict__ H)
{
    size_t i = ((size_t)blockIdx.x * 256 + threadIdx.x) * 4;
    float4 v = *(const float4*)(X + i);
    ushort4 hv;
    hv.x = __half_as_ushort(__float2half_rn(v.x));
    hv.y = __half_as_ushort(__float2half_rn(v.y));
    hv.z = __half_as_ushort(__float2half_rn(v.z));
    hv.w = __half_as_ushort(__float2half_rn(v.w));
    *(ushort4*)(H + i) = hv;
}

// ---------------------------------------------------------------------------
// Weight transpose + fp16: Wt[n][k] = W[k][n]
// ---------------------------------------------------------------------------
__global__ __launch_bounds__(256) void conv_w_t(
    const float* __restrict__ W, __half* __restrict__ H)
{
    __shared__ float tile[32][33];
    const int n0 = blockIdx.x * 32, k0 = blockIdx.y * 32;
    const int tx = threadIdx.x & 31, ty = threadIdx.x >> 5;  // 32x8
    #pragma unroll
    for (int j = 0; j < 32; j += 8)
        tile[ty + j][tx] = W[(size_t)(k0 + ty + j) * EMB + n0 + tx];
    __syncthreads();
    #pragma unroll
    for (int j = 0; j < 32; j += 8)
        H[(size_t)(n0 + ty + j) * EMB + k0 + tx] = __float2half_rn(tile[tx][ty + j]);
}

// ---------------------------------------------------------------------------
// KV summarization: KV[b,h,d,e] = sum_s K[:,d]*V[:,e]; Ksum[b,h,d]
// Register-tiled 4x4 per thread, float4 LDS.
// ---------------------------------------------------------------------------
#define KVCH 16

__global__ __launch_bounds__(256) void kv_partial()
{
    const int bh = blockIdx.x, sp = blockIdx.y;
    const int b = bh / HEADS, h = bh % HEADS;
    const int t = threadIdx.x;
    const int d0 = (t & 15) * 4;
    const int e0 = (t >> 4) * 4;

    __shared__ float Ks[KVCH][HDIM];
    __shared__ float Vs[KVCH][HDIM];

    float acc[4][4];
    #pragma unroll
    for (int i = 0; i < 4; i++)
        #pragma unroll
        for (int j = 0; j < 4; j++) acc[i][j] = 0.f;
    float ksum[4] = {0.f, 0.f, 0.f, 0.f};

    const float* Kbase = g_K + (size_t)b * SEQ * EMB + h * HDIM;
    const float* Vbase = g_V + (size_t)b * SEQ * EMB + h * HDIM;

    const int lr = t >> 4, lc = (t & 15) * 4;   // 16 rows x 16 float4
    const int s_begin = sp * SROWS;
    for (int s0 = s_begin; s0 < s_begin + SROWS; s0 += KVCH) {
        *(float4*)&Ks[lr][lc] = *(const float4*)(Kbase + (size_t)(s0 + lr) * EMB + lc);
        *(float4*)&Vs[lr][lc] = *(const float4*)(Vbase + (size_t)(s0 + lr) * EMB + lc);
        __syncthreads();
        #pragma unroll
        for (int ss = 0; ss < KVCH; ss++) {
            float4 kk = *(const float4*)&Ks[ss][d0];
            float4 vv = *(const float4*)&Vs[ss][e0];
            const float* kp = (const float*)&kk;
            const float* vp = (const float*)&vv;
            #pragma unroll
            for (int i = 0; i < 4; i++) {
                ksum[i] += kp[i];
                #pragma unroll
                for (int j = 0; j < 4; j++)
                    acc[i][j] += kp[i] * vp[j];
            }
        }
        __syncthreads();
    }

    float* KVp = g_KVp + ((size_t)sp * BH + bh) * HDIM * HDIM;
    #pragma unroll
    for (int i = 0; i < 4; i++)
        *(float4*)(KVp + (size_t)(d0 + i) * HDIM + e0) = *(float4*)acc[i];
    if (t < 16) {
        #pragma unroll
        for (int i = 0; i < 4; i++)
            g_Ksump[((size_t)sp * BH + bh) * HDIM + d0 + i] = ksum[i];
    }
}

__global__ __launch_bounds__(256) void kv_reduce()
{
    const int bh = blockIdx.x;
    const int t = threadIdx.x;
    for (int i = t; i < HDIM * HDIM; i += 256) {
        float s = 0.f;
        #pragma unroll
        for (int sp = 0; sp < SPLITS; sp++)
            s += g_KVp[((size_t)sp * BH + bh) * HDIM * HDIM + i];
        g_KV[(size_t)bh * HDIM * HDIM + i] = s;
    }
    if (t < HDIM) {
        float s = 0.f;
        #pragma unroll
        for (int sp = 0; sp < SPLITS; sp++)
            s += g_Ksump[((size_t)sp * BH + bh) * HDIM + t];
        g_Ksum[(size_t)bh * HDIM + t] = s;
    }
}

// ---------------------------------------------------------------------------
// Apply: attn = (Q·KV)/(Q·Ksum+1e-6); writes fp16 operand directly.
// ---------------------------------------------------------------------------
__global__ __launch_bounds__(256) void apply_attn()
{
    const int stile = blockIdx.x;
    const int bh = blockIdx.y;
    const int b = bh / HEADS, h = bh % HEADS;
    const int t = threadIdx.x;

    __shared__ float Qt[HDIM][64];      // Qt[d][row]
    __shared__ float KVs[HDIM][HDIM];
    __shared__ float Ksums[HDIM];

    const int s0 = stile * 64;
    const float* Qbase = g_Q + (size_t)(b * SEQ + s0) * EMB + h * HDIM;

    #pragma unroll
    for (int k = 0; k < 16; k++) {
        int idx = t + 256 * k;
        int rr = idx >> 6, cc = idx & 63;
        Qt[cc][rr] = Qbase[(size_t)rr * EMB + cc];
        KVs[rr][cc] = g_KV[(size_t)bh * HDIM * HDIM + idx];
    }
    if (t < HDIM) Ksums[t] = g_Ksum[(size_t)bh * HDIM + t];
    __syncthreads();

    const int r0 = (t & 15) * 4;
    const int e0 = (t >> 4) * 4;

    float acc[4][4];
    #pragma unroll
    for (int i = 0; i < 4; i++)
        #pragma unroll
        for (int j = 0; j < 4; j++) acc[i][j] = 0.f;
    float nrm[4] = {0.f, 0.f, 0.f, 0.f};

    #pragma unroll
    for (int dd = 0; dd < HDIM; dd++) {
        float4 qq = *(const float4*)&Qt[dd][r0];
        float4 vv = *(const float4*)&KVs[dd][e0];
        const float* qp = (const float*)&qq;
        const float* vp = (const float*)&vv;
        float ks = Ksums[dd];
        #pragma unroll
        for (int i = 0; i < 4; i++) {
            nrm[i] += qp[i] * ks;
            #pragma unroll
            for (int j = 0; j < 4; j++)
                acc[i][j] += qp[i] * vp[j];
        }
    }

    #pragma unroll
    for (int i = 0; i < 4; i++) {
        float inv = 1.f / (nrm[i] + 1e-6f);
        size_t obase = (size_t)(b * SEQ + s0 + r0 + i) * EMB + h * HDIM + e0;
        ushort4 hv;
        hv.x = __half_as_ushort(__float2half_rn(acc[i][0] * inv));
        hv.y = __half_as_ushort(__float2half_rn(acc[i][1] * inv));
        hv.z = __half_as_ushort(__float2half_rn(acc[i][2] * inv));
        hv.w = __half_as_ushort(__float2half_rn(acc[i][3] * inv));
        *(ushort4*)(g_Xh + obase) = hv;
    }
}

// ---------------------------------------------------------------------------
// Launch
// ---------------------------------------------------------------------------
extern "C" void kernel_launch(void* const* d_in, const int* in_sizes, int n_in,
                              void* d_out, int out_size)
{
    const float* query = (const float*)d_in[0];
    const float* keyv  = (const float*)d_in[1];
    const float* W[4] = { (const float*)d_in[2], (const float*)d_in[4],
                          (const float*)d_in[6], (const float*)d_in[8] };
    const float* bq = (const float*)d_in[3];
    const float* bk = (const float*)d_in[5];
    const float* bv = (const float*)d_in[7];
    const float* bo = (const float*)d_in[9];
    float* out = (float*)d_out;

    float *pQ, *pK, *pV;
    __half *pXh;
    __half (*pWh)[(size_t)EMB * EMB];
    cudaGetSymbolAddress((void**)&pQ, g_Q);
    cudaGetSymbolAddress((void**)&pK, g_K);
    cudaGetSymbolAddress((void**)&pV, g_V);
    cudaGetSymbolAddress((void**)&pXh, g_Xh);
    cudaGetSymbolAddress((void**)&pWh, g_Wh);

    static bool attr_set = false;
    if (!attr_set) {
        cudaFuncSetAttribute(gemm_f16, cudaFuncAttributeMaxDynamicSharedMemorySize, SMEM_DYN);
        attr_set = true;
    }

    const dim3 wgrid(EMB / 32, EMB / 32);              // (32, 32)
    const dim3 ggrid(EMB / NTT, ROWS / MT);            // (8, 128)
    const int conv_blocks = (int)(((size_t)ROWS * EMB / 4) / 256);  // 16384

    // Weight transpose + convert
    for (int w = 0; w < 4; w++)
        conv_w_t<<<wgrid, 256>>>(W[w], pWh[w]);

    // Q projection (elu+1 fused)
    conv_f16<<<conv_blocks, 256>>>(query, pXh);
    gemm_f16<<<ggrid, G_THREADS, SMEM_DYN>>>(pXh, pWh[0], bq, pQ, 1);

    // K/V projections (share key_value conversion)
    conv_f16<<<conv_blocks, 256>>>(keyv, pXh);
    gemm_f16<<<ggrid, G_THREADS, SMEM_DYN>>>(pXh, pWh[1], bk, pK, 1);
    gemm_f16<<<ggrid, G_THREADS, SMEM_DYN>>>(pXh, pWh[2], bv, pV, 0);

    // Linear-attention core (fp32)
    kv_partial<<<dim3(BH, SPLITS), 256>>>();
    kv_reduce<<<BH, 256>>>();
    apply_attn<<<dim3(SEQ / 64, BH), 256>>>();   // emits fp16 operand into g_Xh

    // Output projection
    gemm_f16<<<ggrid, G_THREADS, SMEM_DYN>>>(pXh, pWh[3], bo, out, 0);
}